// round 4
// baseline (speedup 1.0000x reference)
#include <cuda_runtime.h>

// RepeatDecoder: B=1024, S=200, H=128, VOCAB=100000
//   features = tanh(hidden + hidden[:,0:1,:])
//   scores   = features @ w_proj + b_proj ; mask PAD/INTEREST -> -inf
//   attn     = softmax(scores, axis=-1)
//   out[b, input_ids[b,s]] += attn[b,s]   (out zero elsewhere)
//
// NOTE: input_ids materializes as int32 (JAX x64 disabled), NOT int64.

#define RD_VOCAB 100000
#define RD_PAD_ID (RD_VOCAB - 2)
#define RD_INTEREST_ID (RD_VOCAB - 1)
#define RD_B 1024
#define RD_S 200
#define RD_H 128
#define RD_THREADS 256

__device__ __forceinline__ float fast_tanhf(float x) {
    float r;
    asm("tanh.approx.f32 %0, %1;" : "=f"(r) : "f"(x));
    return r;
}

__global__ __launch_bounds__(RD_THREADS, 4)
void repeat_decoder_kernel(const float* __restrict__ hidden,
                           const int* __restrict__ ids,
                           const float* __restrict__ w_proj,
                           const float* __restrict__ b_proj,
                           float* __restrict__ out)
{
    __shared__ float s_scores[RD_S];
    __shared__ float s_red[RD_THREADS];

    const int b    = blockIdx.x;
    const int tid  = threadIdx.x;
    const int warp = tid >> 5;
    const int lane = tid & 31;

    const float* hb = hidden + (size_t)b * RD_S * RD_H;

    // Per-lane constants: 4 elems of w_proj and of keys (= hidden[b,0,:])
    const float4 w4 = reinterpret_cast<const float4*>(w_proj)[lane];
    const float4 k4 = reinterpret_cast<const float4*>(hb)[lane];
    const float  bias = b_proj[0];

    // --- Phase 1: scores, warp-per-position (8 warps, 25 iters) ---
    for (int s = warp; s < RD_S; s += (RD_THREADS / 32)) {
        const float4 h4 = reinterpret_cast<const float4*>(hb + s * RD_H)[lane];
        float p = fast_tanhf(h4.x + k4.x) * w4.x;
        p = fmaf(fast_tanhf(h4.y + k4.y), w4.y, p);
        p = fmaf(fast_tanhf(h4.z + k4.z), w4.z, p);
        p = fmaf(fast_tanhf(h4.w + k4.w), w4.w, p);
        #pragma unroll
        for (int off = 16; off > 0; off >>= 1)
            p += __shfl_xor_sync(0xFFFFFFFFu, p, off);
        if (lane == 0) s_scores[s] = p + bias;
    }
    __syncthreads();

    // --- Phase 2: mask + softmax over S=200 (block reductions) ---
    int my_id = 0;
    bool valid = false;
    float my_score = -INFINITY;
    if (tid < RD_S) {
        my_id = ids[(size_t)b * RD_S + tid];
        valid = (my_id != RD_PAD_ID) && (my_id != RD_INTEREST_ID);
        my_score = valid ? s_scores[tid] : -INFINITY;
    }

    s_red[tid] = my_score;
    __syncthreads();
    #pragma unroll
    for (int off = RD_THREADS / 2; off > 0; off >>= 1) {
        if (tid < off) s_red[tid] = fmaxf(s_red[tid], s_red[tid + off]);
        __syncthreads();
    }
    const float mx = s_red[0];
    __syncthreads();

    const float e = valid ? __expf(my_score - mx) : 0.0f;
    s_red[tid] = e;
    __syncthreads();
    #pragma unroll
    for (int off = RD_THREADS / 2; off > 0; off >>= 1) {
        if (tid < off) s_red[tid] += s_red[tid + off];
        __syncthreads();
    }
    const float wgt = e * (1.0f / s_red[0]);

    // --- Phase 3: zero this batch's output row (400 KB, float4 stores) ---
    float* row = out + (size_t)b * RD_VOCAB;
    float4* row4 = reinterpret_cast<float4*>(row);
    const float4 z = make_float4(0.f, 0.f, 0.f, 0.f);
    #pragma unroll 4
    for (int i = tid; i < RD_VOCAB / 4; i += RD_THREADS)
        row4[i] = z;
    __syncthreads();

    // --- Phase 4: scatter-add attention weights (row is block-private) ---
    if (tid < RD_S && valid)
        atomicAdd(row + my_id, wgt);
}

extern "C" void kernel_launch(void* const* d_in, const int* in_sizes, int n_in,
                              void* d_out, int out_size)
{
    const float* hidden = (const float*)d_in[0];
    const int*   ids    = (const int*)d_in[1];
    const float* w_proj = (const float*)d_in[2];
    const float* b_proj = (const float*)d_in[3];
    float*       out    = (float*)d_out;

    repeat_decoder_kernel<<<RD_B, RD_THREADS>>>(hidden, ids, w_proj, b_proj, out);
}